// round 4
// baseline (speedup 1.0000x reference)
#include <cuda_runtime.h>
#include <cuda_bf16.h>
#include <math.h>

// ---------------------------------------------------------------------------
// GraphSAGE (3-layer) on GB300 — tensor-core edition (3xTF32 mma.sync).
//   L1: h1 = relu( mean_agg(x) @ W1l + x @ W1r + b1 )           [N,256]
//   L2: h2 = relu( mean_agg(h1 @ W2l) + h1 @ W2r + b2 )         [N,128]
//   L3: out = log_softmax( mean_agg(h2 @ W3l) + h2 @ W3r + b3 ) [N,64]
// ---------------------------------------------------------------------------

#define N_NODES 100000
#define E_EDGES 600000

__device__ float g_agg [N_NODES * 128];
__device__ float g_h1  [N_NODES * 256];
__device__ float g_p2l [N_NODES * 128];
__device__ float g_p2r [N_NODES * 128];
__device__ float g_h2  [N_NODES * 128];
__device__ float g_p3l [N_NODES * 64];
__device__ float g_p3r [N_NODES * 64];
__device__ int   g_rowptr[N_NODES + 1];
__device__ int   g_cnt   [N_NODES];
__device__ int   g_esrc  [E_EDGES];
__device__ int   g_edge  [2 * E_EDGES];
__device__ int   g_is64;

// ---------------------------------------------------------------------------
// Edge dtype detection + normalization
// ---------------------------------------------------------------------------
__global__ void detect_kernel(const int* __restrict__ buf) {
    if (blockIdx.x == 0 && threadIdx.x == 0) {
        int all0 = 1;
        for (int i = 0; i < 128; i++)
            if (buf[2 * i + 1] != 0) { all0 = 0; break; }
        g_is64 = all0;
    }
}

__global__ void convert_kernel(const int* __restrict__ buf, int e2) {
    int i = blockIdx.x * blockDim.x + threadIdx.x;
    if (i < e2) {
        int v = g_is64 ? buf[2 * i] : buf[i];
        v = min(max(v, 0), N_NODES - 1);
        g_edge[i] = v;
    }
}

// ---------------------------------------------------------------------------
// CSR build
// ---------------------------------------------------------------------------
__global__ void zero_cnt_kernel(int n) {
    int i = blockIdx.x * blockDim.x + threadIdx.x;
    if (i < n) g_cnt[i] = 0;
}

__global__ void hist_kernel(int e) {
    int i = blockIdx.x * blockDim.x + threadIdx.x;
    if (i < e) atomicAdd(&g_cnt[g_edge[E_EDGES + i]], 1);
}

__global__ void scan_kernel(int n) {
    const int T = 1024;
    __shared__ int sums[T];
    int tid = threadIdx.x;
    int chunk = (n + T - 1) / T;
    int beg = min(tid * chunk, n);
    int end = min(beg + chunk, n);
    int s = 0;
    for (int i = beg; i < end; i++) s += g_cnt[i];
    sums[tid] = s;
    __syncthreads();
    for (int off = 1; off < T; off <<= 1) {
        int t = (tid >= off) ? sums[tid - off] : 0;
        __syncthreads();
        sums[tid] += t;
        __syncthreads();
    }
    int run = sums[tid] - s;
    for (int i = beg; i < end; i++) { g_rowptr[i] = run; run += g_cnt[i]; }
    if (tid == T - 1) g_rowptr[n] = sums[T - 1];
}

__global__ void cursor_kernel(int n) {
    int i = blockIdx.x * blockDim.x + threadIdx.x;
    if (i < n) g_cnt[i] = g_rowptr[i];
}

__global__ void fill_kernel(int e) {
    int i = blockIdx.x * blockDim.x + threadIdx.x;
    if (i < e) {
        int d = g_edge[E_EDGES + i];
        int pos = atomicAdd(&g_cnt[d], 1);
        if (pos >= 0 && pos < E_EDGES) g_esrc[pos] = g_edge[i];
    }
}

// ---------------------------------------------------------------------------
// Aggregation kernels (one warp per node)
// ---------------------------------------------------------------------------
__global__ void agg_mean128_kernel(const float* __restrict__ X,
                                   float* __restrict__ out, int n) {
    int gid  = blockIdx.x * blockDim.x + threadIdx.x;
    int node = gid >> 5;
    int lane = gid & 31;
    if (node >= n) return;
    int s0 = g_rowptr[node], s1 = g_rowptr[node + 1];
    float4 acc = make_float4(0.f, 0.f, 0.f, 0.f);
    for (int j = s0; j < s1; j++) {
        int s = g_esrc[j];
        float4 v = ((const float4*)(X + (size_t)s * 128))[lane];
        acc.x += v.x; acc.y += v.y; acc.z += v.z; acc.w += v.w;
    }
    float inv = 1.0f / (float)max(s1 - s0, 1);
    acc.x *= inv; acc.y *= inv; acc.z *= inv; acc.w *= inv;
    ((float4*)(out + (size_t)node * 128))[lane] = acc;
}

__global__ void agg_add_relu128_kernel(const float* __restrict__ Pl,
                                       const float* __restrict__ Pr,
                                       float* __restrict__ out, int n) {
    int gid  = blockIdx.x * blockDim.x + threadIdx.x;
    int node = gid >> 5;
    int lane = gid & 31;
    if (node >= n) return;
    int s0 = g_rowptr[node], s1 = g_rowptr[node + 1];
    float4 acc = make_float4(0.f, 0.f, 0.f, 0.f);
    for (int j = s0; j < s1; j++) {
        int s = g_esrc[j];
        float4 v = ((const float4*)(Pl + (size_t)s * 128))[lane];
        acc.x += v.x; acc.y += v.y; acc.z += v.z; acc.w += v.w;
    }
    float inv = 1.0f / (float)max(s1 - s0, 1);
    float4 r = ((const float4*)(Pr + (size_t)node * 128))[lane];
    float4 o;
    o.x = fmaxf(acc.x * inv + r.x, 0.f);
    o.y = fmaxf(acc.y * inv + r.y, 0.f);
    o.z = fmaxf(acc.z * inv + r.z, 0.f);
    o.w = fmaxf(acc.w * inv + r.w, 0.f);
    ((float4*)(out + (size_t)node * 128))[lane] = o;
}

__global__ void agg_add_lsm64_kernel(const float* __restrict__ Pl,
                                     const float* __restrict__ Pr,
                                     float* __restrict__ out, int n) {
    int gid  = blockIdx.x * blockDim.x + threadIdx.x;
    int node = gid >> 5;
    int lane = gid & 31;
    if (node >= n) return;
    int s0 = g_rowptr[node], s1 = g_rowptr[node + 1];
    float2 acc = make_float2(0.f, 0.f);
    for (int j = s0; j < s1; j++) {
        int s = g_esrc[j];
        float2 v = ((const float2*)(Pl + (size_t)s * 64))[lane];
        acc.x += v.x; acc.y += v.y;
    }
    float inv = 1.0f / (float)max(s1 - s0, 1);
    float2 r = ((const float2*)(Pr + (size_t)node * 64))[lane];
    float2 v;
    v.x = acc.x * inv + r.x;
    v.y = acc.y * inv + r.y;
    float m = fmaxf(v.x, v.y);
    #pragma unroll
    for (int off = 16; off >= 1; off >>= 1)
        m = fmaxf(m, __shfl_xor_sync(0xFFFFFFFFu, m, off));
    float se = expf(v.x - m) + expf(v.y - m);
    #pragma unroll
    for (int off = 16; off >= 1; off >>= 1)
        se += __shfl_xor_sync(0xFFFFFFFFu, se, off);
    float lse = m + logf(se);
    float2 o; o.x = v.x - lse; o.y = v.y - lse;
    ((float2*)(out + (size_t)node * 64))[lane] = o;
}

// ---------------------------------------------------------------------------
// 3xTF32 tensor-core GEMM.
//   C[M,N] = A0[M,K0]@B0[K0,N] + A1[M,K1]@B1[K1,N] (+bias)(+relu)
// BM=128, BN in {128,64}, BK=16. 256 threads = 8 warps arranged 4(M) x 2(N).
// Fragments loaded with plain LDS (no ldmatrix for 32-bit types).
// ---------------------------------------------------------------------------
__device__ __forceinline__ unsigned f2tf32(float f) {
    unsigned r;
    asm("cvt.rna.tf32.f32 %0, %1;" : "=r"(r) : "f"(f));
    return r;
}

__device__ __forceinline__ void mma_tf32(float c[4], const unsigned a[4],
                                         unsigned b0, unsigned b1) {
    asm volatile(
        "mma.sync.aligned.m16n8k8.row.col.f32.tf32.tf32.f32 "
        "{%0,%1,%2,%3},{%4,%5,%6,%7},{%8,%9},{%0,%1,%2,%3};"
        : "+f"(c[0]), "+f"(c[1]), "+f"(c[2]), "+f"(c[3])
        : "r"(a[0]), "r"(a[1]), "r"(a[2]), "r"(a[3]), "r"(b0), "r"(b1));
}

template <int BM, int BN, int BK>
__global__ __launch_bounds__(256)
void gemm3tf32_kernel(const float* __restrict__ A0, int K0, const float* __restrict__ B0,
                      const float* __restrict__ A1, int K1, const float* __restrict__ B1,
                      const float* __restrict__ bias, float* __restrict__ C,
                      int M, int N, int relu) {
    constexpr int THREADS = 256;
    constexpr int WM = 4, WN = 2;
    constexpr int WTM = BM / WM;               // 32
    constexpr int WTN = BN / WN;               // 64 or 32
    constexpr int MF = WTM / 16;               // 2
    constexpr int NF = WTN / 8;                // 8 or 4
    constexpr int LDS = BK + 4;                // padded stride (b32 words)

    __shared__ unsigned Ah[BM][LDS], Al[BM][LDS];
    __shared__ unsigned Bh[BN][LDS], Bl[BN][LDS];

    const int tid  = threadIdx.x;
    const int warp = tid >> 5;
    const int lane = tid & 31;
    const int wm   = warp >> 1;
    const int wn   = warp & 1;
    const int row0 = blockIdx.y * BM;
    const int col0 = blockIdx.x * BN;
    const int qr   = lane >> 2;                // 0..7
    const int qc   = lane & 3;                 // 0..3

    float acc[MF][NF][4];
    #pragma unroll
    for (int i = 0; i < MF; i++)
        #pragma unroll
        for (int j = 0; j < NF; j++)
            #pragma unroll
            for (int r = 0; r < 4; r++) acc[i][j][r] = 0.f;

    const int kt0 = K0 / BK;
    const int kt1 = K1 / BK;

    for (int kt = 0; kt < kt0 + kt1; kt++) {
        const float* A; const float* B; int kbase, K_;
        if (kt < kt0) { A = A0; B = B0; kbase = kt * BK;         K_ = K0; }
        else          { A = A1; B = B1; kbase = (kt - kt0) * BK; K_ = K1; }

        // ---- A tile: BM x BK row-major, float4 global loads, hi/lo split ----
        #pragma unroll
        for (int t = 0; t < (BM * BK / 4) / THREADS; t++) {
            int idx4 = tid + t * THREADS;
            int m  = idx4 >> 2;                 // BK/4 == 4
            int k4 = (idx4 & 3) * 4;
            int gm = row0 + m;
            float4 v = make_float4(0.f, 0.f, 0.f, 0.f);
            if (gm < M) v = *(const float4*)&A[(size_t)gm * K_ + kbase + k4];
            float f[4] = {v.x, v.y, v.z, v.w};
            #pragma unroll
            for (int j = 0; j < 4; j++) {
                unsigned hi = f2tf32(f[j]);
                float lo = f[j] - __uint_as_float(hi);
                Ah[m][k4 + j] = hi;
                Al[m][k4 + j] = f2tf32(lo);
            }
        }
        // ---- B tile: BK x BN global, stored n-major (BN x BK) ----
        #pragma unroll
        for (int t = 0; t < (BN * BK / 4) / THREADS; t++) {
            int idx4 = tid + t * THREADS;
            int n4 = (idx4 % (BN / 4)) * 4;
            int k  = idx4 / (BN / 4);
            float4 v = *(const float4*)&B[(size_t)(kbase + k) * N + col0 + n4];
            float f[4] = {v.x, v.y, v.z, v.w};
            #pragma unroll
            for (int j = 0; j < 4; j++) {
                unsigned hi = f2tf32(f[j]);
                float lo = f[j] - __uint_as_float(hi);
                Bh[n4 + j][k] = hi;
                Bl[n4 + j][k] = f2tf32(lo);
            }
        }
        __syncthreads();

        // ---- two k8 steps ----
        #pragma unroll
        for (int kk = 0; kk < BK; kk += 8) {
            unsigned ah[MF][4], al[MF][4], bh[NF][2], bl[NF][2];
            #pragma unroll
            for (int mi = 0; mi < MF; mi++) {
                int m0 = wm * WTM + mi * 16 + qr;
                ah[mi][0] = Ah[m0    ][kk + qc];
                ah[mi][1] = Ah[m0 + 8][kk + qc];
                ah[mi][2] = Ah[m0    ][kk + 4 + qc];
                ah[mi][3] = Ah[m0 + 8][kk + 4 + qc];
                al[mi][0] = Al[m0    ][kk + qc];
                al[mi][1] = Al[m0 + 8][kk + qc];
                al[mi][2] = Al[m0    ][kk + 4 + qc];
                al[mi][3] = Al[m0 + 8][kk + 4 + qc];
            }
            #pragma unroll
            for (int nj = 0; nj < NF; nj++) {
                int n = wn * WTN + nj * 8 + qr;
                bh[nj][0] = Bh[n][kk + qc];
                bh[nj][1] = Bh[n][kk + 4 + qc];
                bl[nj][0] = Bl[n][kk + qc];
                bl[nj][1] = Bl[n][kk + 4 + qc];
            }
            #pragma unroll
            for (int mi = 0; mi < MF; mi++)
                #pragma unroll
                for (int nj = 0; nj < NF; nj++) {
                    mma_tf32(acc[mi][nj], ah[mi], bh[nj][0], bh[nj][1]);
                    mma_tf32(acc[mi][nj], ah[mi], bl[nj][0], bl[nj][1]);
                    mma_tf32(acc[mi][nj], al[mi], bh[nj][0], bh[nj][1]);
                }
        }
        __syncthreads();
    }

    // ---- epilogue: bias / relu, float2 stores ----
    #pragma unroll
    for (int mi = 0; mi < MF; mi++) {
        int r0 = row0 + wm * WTM + mi * 16 + qr;
        int r1 = r0 + 8;
        #pragma unroll
        for (int nj = 0; nj < NF; nj++) {
            int col = col0 + wn * WTN + nj * 8 + qc * 2;
            float bx = 0.f, by = 0.f;
            if (bias) { bx = bias[col]; by = bias[col + 1]; }
            float c0 = acc[mi][nj][0] + bx, c1 = acc[mi][nj][1] + by;
            float c2 = acc[mi][nj][2] + bx, c3 = acc[mi][nj][3] + by;
            if (relu) {
                c0 = fmaxf(c0, 0.f); c1 = fmaxf(c1, 0.f);
                c2 = fmaxf(c2, 0.f); c3 = fmaxf(c3, 0.f);
            }
            if (r0 < M) *(float2*)&C[(size_t)r0 * N + col] = make_float2(c0, c1);
            if (r1 < M) *(float2*)&C[(size_t)r1 * N + col] = make_float2(c2, c3);
        }
    }
}

// ---------------------------------------------------------------------------
extern "C" void kernel_launch(void* const* d_in, const int* in_sizes, int n_in,
                              void* d_out, int out_size) {
    const float* x   = (const float*)d_in[0];
    const int*   ei  = (const int*)d_in[1];
    const float* W1l = (const float*)d_in[2];
    const float* W1r = (const float*)d_in[3];
    const float* b1  = (const float*)d_in[4];
    const float* W2l = (const float*)d_in[5];
    const float* W2r = (const float*)d_in[6];
    const float* b2  = (const float*)d_in[7];
    const float* W3l = (const float*)d_in[8];
    const float* W3r = (const float*)d_in[9];
    const float* b3  = (const float*)d_in[10];
    float* out = (float*)d_out;

    const int N = N_NODES;
    const int E = E_EDGES;

    float *p_agg, *p_h1, *p_p2l, *p_p2r, *p_h2, *p_p3l, *p_p3r;
    cudaGetSymbolAddress((void**)&p_agg, g_agg);
    cudaGetSymbolAddress((void**)&p_h1,  g_h1);
    cudaGetSymbolAddress((void**)&p_p2l, g_p2l);
    cudaGetSymbolAddress((void**)&p_p2r, g_p2r);
    cudaGetSymbolAddress((void**)&p_h2,  g_h2);
    cudaGetSymbolAddress((void**)&p_p3l, g_p3l);
    cudaGetSymbolAddress((void**)&p_p3r, g_p3r);

    const int TB = 256;
    dim3 gN((N + TB - 1) / TB);
    dim3 gE((E + TB - 1) / TB);
    dim3 gE2((2 * E + TB - 1) / TB);
    dim3 gWarp(((size_t)N * 32 + TB - 1) / TB);

    // ---- edge normalization + CSR ----
    detect_kernel<<<1, 1>>>(ei);
    convert_kernel<<<gE2, TB>>>(ei, 2 * E);
    zero_cnt_kernel<<<gN, TB>>>(N);
    hist_kernel<<<gE, TB>>>(E);
    scan_kernel<<<1, 1024>>>(N);
    cursor_kernel<<<gN, TB>>>(N);
    fill_kernel<<<gE, TB>>>(E);

    const int MT = (N + 127) / 128;
    dim3 g256(2, MT);
    dim3 g128(1, MT);
    dim3 g64 (1, MT);

    // ---- Layer 1 ----
    agg_mean128_kernel<<<gWarp, TB>>>(x, p_agg, N);
    gemm3tf32_kernel<128, 128, 16><<<g256, 256>>>(
        p_agg, 128, W1l, x, 128, W1r, b1, p_h1, N, 256, 1);

    // ---- Layer 2 ----
    gemm3tf32_kernel<128, 128, 16><<<g128, 256>>>(
        p_h1, 256, W2l, (const float*)0, 0, (const float*)0,
        (const float*)0, p_p2l, N, 128, 0);
    gemm3tf32_kernel<128, 128, 16><<<g128, 256>>>(
        p_h1, 256, W2r, (const float*)0, 0, (const float*)0,
        b2, p_p2r, N, 128, 0);
    agg_add_relu128_kernel<<<gWarp, TB>>>(p_p2l, p_p2r, p_h2, N);

    // ---- Layer 3 ----
    gemm3tf32_kernel<128, 64, 16><<<g64, 256>>>(
        p_h2, 128, W3l, (const float*)0, 0, (const float*)0,
        (const float*)0, p_p3l, N, 64, 0);
    gemm3tf32_kernel<128, 64, 16><<<g64, 256>>>(
        p_h2, 128, W3r, (const float*)0, 0, (const float*)0,
        b3, p_p3r, N, 64, 0);
    agg_add_lsm64_kernel<<<gWarp, TB>>>(p_p3l, p_p3r, out, N);
}

// round 16
// speedup vs baseline: 2.1753x; 2.1753x over previous
#include <cuda_runtime.h>
#include <cuda_bf16.h>
#include <math.h>

// ---------------------------------------------------------------------------
// GraphSAGE (3-layer) on GB300 — split-bf16 tensor-core edition.
//   L1: h1 = relu( mean_agg(x) @ W1l + x @ W1r + b1 )           [N,256]
//   L2: h2 = relu( mean_agg(h1 @ W2l) + h1 @ W2r + b2 )         [N,128]
//   L3: out = log_softmax( mean_agg(h2 @ W3l) + h2 @ W3r + b3 ) [N,64]
// GEMMs: mma.sync.m16n8k16 bf16, 3-term hi/lo split (~1e-5 accuracy).
// All GEMM operands live in global memory in mma FRAGMENT ORDER, written by
// their producers; the GEMM mainloop is cp.async double-buffered with zero
// conversion and minimal LDS.
// ---------------------------------------------------------------------------

#define N_NODES 100000
#define E_EDGES 600000
#define ROWS_PAD 100096   // 782 * 128

// ---- frag-order operand buffers (uint4 = 16B aligned) ----
__device__ uint4 g_a1h[(size_t)ROWS_PAD * 32];  // [agg | x] K=256 hi
__device__ uint4 g_a1l[(size_t)ROWS_PAD * 32];
__device__ uint4 g_h1h[(size_t)ROWS_PAD * 32];  // h1 K=256
__device__ uint4 g_h1l[(size_t)ROWS_PAD * 32];
__device__ uint4 g_h2h[(size_t)ROWS_PAD * 16];  // h2 K=128
__device__ uint4 g_h2l[(size_t)ROWS_PAD * 16];
__device__ uint4 g_w1h[8192],  g_w1l[8192];     // [W1l;W1r] K=256,N=256
__device__ uint4 g_w2lh[4096], g_w2ll[4096];    // K=256,N=128
__device__ uint4 g_w2rh[4096], g_w2rl[4096];
__device__ uint4 g_w3lh[1024], g_w3ll[1024];    // K=128,N=64
__device__ uint4 g_w3rh[1024], g_w3rl[1024];

// ---- fp32 scratch ----
__device__ float g_p2l[(size_t)ROWS_PAD * 128];
__device__ float g_p2r[(size_t)ROWS_PAD * 128];
__device__ float g_p3l[(size_t)ROWS_PAD * 64];
__device__ float g_p3r[(size_t)ROWS_PAD * 64];

// ---- CSR ----
__device__ int g_rowptr[N_NODES + 1];
__device__ int g_cnt[N_NODES];
__device__ int g_esrc[E_EDGES];
__device__ int g_edge[2 * E_EDGES];
__device__ int g_is64;

// ---------------------------------------------------------------------------
// helpers
// ---------------------------------------------------------------------------
__device__ __forceinline__ void split2(float a, float b, unsigned& hi, unsigned& lo) {
    __nv_bfloat16 ah = __float2bfloat16(a);
    __nv_bfloat16 bh = __float2bfloat16(b);
    __nv_bfloat16 al = __float2bfloat16(a - __bfloat162float(ah));
    __nv_bfloat16 bl = __float2bfloat16(b - __bfloat162float(bh));
    hi = (unsigned)__bfloat16_as_ushort(ah) | ((unsigned)__bfloat16_as_ushort(bh) << 16);
    lo = (unsigned)__bfloat16_as_ushort(al) | ((unsigned)__bfloat16_as_ushort(bl) << 16);
}

// u32-word index of the bf16x2 pair (k even) for A-operand fragment layout.
__device__ __forceinline__ size_t fragA_u32(int m, int k, int K) {
    return ((((size_t)(m >> 4)) * (K >> 4) + (k >> 4)) * 32 +
            (((m & 7) << 2) | ((k & 7) >> 1))) * 4 +
           ((m >> 3) & 1) + (((k >> 3) & 1) << 1);
}
// B-operand (weights): [n8-group][k16][32 lanes][2 words]
__device__ __forceinline__ size_t fragB_u32(int k, int n, int K) {
    return ((((size_t)(n >> 3)) * (K >> 4) + (k >> 4)) * 32 +
            (((n & 7) << 2) | ((k & 7) >> 1))) * 2 +
           ((k >> 3) & 1);
}

__device__ __forceinline__ void cp16(void* dst, const void* src) {
    unsigned d = (unsigned)__cvta_generic_to_shared(dst);
    asm volatile("cp.async.cg.shared.global [%0], [%1], 16;" :: "r"(d), "l"(src));
}
__device__ __forceinline__ void cp_commit() { asm volatile("cp.async.commit_group;"); }
template <int N>
__device__ __forceinline__ void cp_wait() { asm volatile("cp.async.wait_group %0;" :: "n"(N)); }

__device__ __forceinline__ void mma_bf16(float* c, const uint4& a, const uint2& b) {
    asm volatile(
        "mma.sync.aligned.m16n8k16.row.col.f32.bf16.bf16.f32 "
        "{%0,%1,%2,%3},{%4,%5,%6,%7},{%8,%9},{%0,%1,%2,%3};"
        : "+f"(c[0]), "+f"(c[1]), "+f"(c[2]), "+f"(c[3])
        : "r"(a.x), "r"(a.y), "r"(a.z), "r"(a.w), "r"(b.x), "r"(b.y));
}

// ---------------------------------------------------------------------------
// Edge dtype detection + normalization + CSR build (validated in R2/R4)
// ---------------------------------------------------------------------------
__global__ void detect_kernel(const int* __restrict__ buf) {
    if (blockIdx.x == 0 && threadIdx.x == 0) {
        int all0 = 1;
        for (int i = 0; i < 128; i++)
            if (buf[2 * i + 1] != 0) { all0 = 0; break; }
        g_is64 = all0;
    }
}
__global__ void convert_kernel(const int* __restrict__ buf, int e2) {
    int i = blockIdx.x * blockDim.x + threadIdx.x;
    if (i < e2) {
        int v = g_is64 ? buf[2 * i] : buf[i];
        g_edge[i] = min(max(v, 0), N_NODES - 1);
    }
}
__global__ void zero_cnt_kernel(int n) {
    int i = blockIdx.x * blockDim.x + threadIdx.x;
    if (i < n) g_cnt[i] = 0;
}
__global__ void hist_kernel(int e) {
    int i = blockIdx.x * blockDim.x + threadIdx.x;
    if (i < e) atomicAdd(&g_cnt[g_edge[E_EDGES + i]], 1);
}
__global__ void scan_kernel(int n) {
    const int T = 1024;
    __shared__ int sums[T];
    int tid = threadIdx.x;
    int chunk = (n + T - 1) / T;
    int beg = min(tid * chunk, n);
    int end = min(beg + chunk, n);
    int s = 0;
    for (int i = beg; i < end; i++) s += g_cnt[i];
    sums[tid] = s;
    __syncthreads();
    for (int off = 1; off < T; off <<= 1) {
        int t = (tid >= off) ? sums[tid - off] : 0;
        __syncthreads();
        sums[tid] += t;
        __syncthreads();
    }
    int run = sums[tid] - s;
    for (int i = beg; i < end; i++) { g_rowptr[i] = run; run += g_cnt[i]; }
    if (tid == T - 1) g_rowptr[n] = sums[T - 1];
}
__global__ void cursor_kernel(int n) {
    int i = blockIdx.x * blockDim.x + threadIdx.x;
    if (i < n) g_cnt[i] = g_rowptr[i];
}
__global__ void fill_kernel(int e) {
    int i = blockIdx.x * blockDim.x + threadIdx.x;
    if (i < e) {
        int d = g_edge[E_EDGES + i];
        int pos = atomicAdd(&g_cnt[d], 1);
        if (pos >= 0 && pos < E_EDGES) g_esrc[pos] = g_edge[i];
    }
}

// ---------------------------------------------------------------------------
// Operand preparation
// ---------------------------------------------------------------------------
// x -> frag-order hi/lo at k offset +128 of the K=256 concat space
__global__ void xprep_kernel(const float* __restrict__ X,
                             unsigned* __restrict__ dh, unsigned* __restrict__ dl, int n) {
    int idx = blockIdx.x * blockDim.x + threadIdx.x;
    if (idx >= n * 32) return;
    int m = idx >> 5, j = idx & 31;
    float4 v = ((const float4*)X)[(size_t)m * 32 + j];
    unsigned h0, l0, h1, l1;
    split2(v.x, v.y, h0, l0);
    split2(v.z, v.w, h1, l1);
    size_t o = fragA_u32(m, 4 * j + 128, 256);
    dh[o] = h0; dl[o] = l0; dh[o + 4] = h1; dl[o + 4] = l1;
}

// weight [K x Nf] fp32 row-major -> frag-order hi/lo (with k offset into Ktot)
__global__ void wprep_kernel(const float* __restrict__ W, int K, int Nf, int koff, int Ktot,
                             unsigned* __restrict__ dh, unsigned* __restrict__ dl) {
    int idx = blockIdx.x * blockDim.x + threadIdx.x;
    if (idx >= (K >> 1) * Nf) return;
    int n = idx % Nf, k = (idx / Nf) * 2;
    unsigned h, l;
    split2(W[(size_t)k * Nf + n], W[(size_t)(k + 1) * Nf + n], h, l);
    size_t o = fragB_u32(k + koff, n, Ktot);
    dh[o] = h; dl[o] = l;
}

// ---------------------------------------------------------------------------
// Aggregation kernels (one warp per node); frag-order bf16 hi/lo outputs
// ---------------------------------------------------------------------------
__global__ void agg_mean_frag_kernel(const float* __restrict__ X,
                                     unsigned* __restrict__ dh,
                                     unsigned* __restrict__ dl, int n) {
    int gid  = blockIdx.x * blockDim.x + threadIdx.x;
    int node = gid >> 5;
    int lane = gid & 31;
    if (node >= n) return;
    int s0 = g_rowptr[node], s1 = g_rowptr[node + 1];
    float4 acc = make_float4(0.f, 0.f, 0.f, 0.f);
    for (int j = s0; j < s1; j++) {
        int s = g_esrc[j];
        float4 v = ((const float4*)(X + (size_t)s * 128))[lane];
        acc.x += v.x; acc.y += v.y; acc.z += v.z; acc.w += v.w;
    }
    float inv = 1.0f / (float)max(s1 - s0, 1);
    acc.x *= inv; acc.y *= inv; acc.z *= inv; acc.w *= inv;
    unsigned h0, l0, h1, l1;
    split2(acc.x, acc.y, h0, l0);
    split2(acc.z, acc.w, h1, l1);
    size_t o = fragA_u32(node, 4 * lane, 256);
    dh[o] = h0; dl[o] = l0; dh[o + 4] = h1; dl[o + 4] = l1;
}

__global__ void agg_add_relu_frag_kernel(const float* __restrict__ Pl,
                                         const float* __restrict__ Pr,
                                         unsigned* __restrict__ dh,
                                         unsigned* __restrict__ dl, int n) {
    int gid  = blockIdx.x * blockDim.x + threadIdx.x;
    int node = gid >> 5;
    int lane = gid & 31;
    if (node >= n) return;
    int s0 = g_rowptr[node], s1 = g_rowptr[node + 1];
    float4 acc = make_float4(0.f, 0.f, 0.f, 0.f);
    for (int j = s0; j < s1; j++) {
        int s = g_esrc[j];
        float4 v = ((const float4*)(Pl + (size_t)s * 128))[lane];
        acc.x += v.x; acc.y += v.y; acc.z += v.z; acc.w += v.w;
    }
    float inv = 1.0f / (float)max(s1 - s0, 1);
    float4 r = ((const float4*)(Pr + (size_t)node * 128))[lane];
    float o0 = fmaxf(acc.x * inv + r.x, 0.f);
    float o1 = fmaxf(acc.y * inv + r.y, 0.f);
    float o2 = fmaxf(acc.z * inv + r.z, 0.f);
    float o3 = fmaxf(acc.w * inv + r.w, 0.f);
    unsigned h0, l0, h1, l1;
    split2(o0, o1, h0, l0);
    split2(o2, o3, h1, l1);
    size_t o = fragA_u32(node, 4 * lane, 128);
    dh[o] = h0; dl[o] = l0; dh[o + 4] = h1; dl[o + 4] = l1;
}

__global__ void agg_add_lsm64_kernel(const float* __restrict__ Pl,
                                     const float* __restrict__ Pr,
                                     float* __restrict__ out, int n) {
    int gid  = blockIdx.x * blockDim.x + threadIdx.x;
    int node = gid >> 5;
    int lane = gid & 31;
    if (node >= n) return;
    int s0 = g_rowptr[node], s1 = g_rowptr[node + 1];
    float2 acc = make_float2(0.f, 0.f);
    for (int j = s0; j < s1; j++) {
        int s = g_esrc[j];
        float2 v = ((const float2*)(Pl + (size_t)s * 64))[lane];
        acc.x += v.x; acc.y += v.y;
    }
    float inv = 1.0f / (float)max(s1 - s0, 1);
    float2 r = ((const float2*)(Pr + (size_t)node * 64))[lane];
    float2 v;
    v.x = acc.x * inv + r.x;
    v.y = acc.y * inv + r.y;
    float m = fmaxf(v.x, v.y);
    #pragma unroll
    for (int off = 16; off >= 1; off >>= 1)
        m = fmaxf(m, __shfl_xor_sync(0xFFFFFFFFu, m, off));
    float se = expf(v.x - m) + expf(v.y - m);
    #pragma unroll
    for (int off = 16; off >= 1; off >>= 1)
        se += __shfl_xor_sync(0xFFFFFFFFu, se, off);
    float lse = m + logf(se);
    ((float2*)(out + (size_t)node * 64))[lane] = make_float2(v.x - lse, v.y - lse);
}

// ---------------------------------------------------------------------------
// Split-bf16 GEMM: C[M,Nfull] = A @ B (+bias)(+relu), 3 mma terms.
// BM=128, BK=32, 256 threads (8 warps, 4x2). FRAG_OUT: emit frag-order hi/lo
// (next layer's A), else fp32 row-major.
// ---------------------------------------------------------------------------
template <int BN, bool FRAG_OUT>
__global__ __launch_bounds__(256)
void gemm_bf16_kernel(const uint4* __restrict__ Agh, const uint4* __restrict__ Agl,
                      const uint4* __restrict__ Bgh, const uint4* __restrict__ Bgl,
                      int K, int Nfull, const float* __restrict__ bias,
                      float* __restrict__ C,
                      uint4* __restrict__ Oh, uint4* __restrict__ Ol,
                      int relu) {
    constexpr int A_U4 = 512;           // 8 row-tiles * 2 k16 * 32 lanes
    constexpr int NB8  = BN / 8;
    constexpr int B_U2 = NB8 * 64;      // NB8 * 2 k16 * 32 lanes
    constexpr int WTN  = BN / 2;
    constexpr int NF   = WTN / 8;

    extern __shared__ char sm[];
    uint4* sAh = (uint4*)sm;                    // [2][A_U4]
    uint4* sAl = sAh + 2 * A_U4;
    uint2* sBh = (uint2*)(sAl + 2 * A_U4);      // [2][B_U2]
    uint2* sBl = sBh + 2 * B_U2;

    const int tid  = threadIdx.x;
    const int warp = tid >> 5;
    const int lane = tid & 31;
    const int wm   = warp >> 1;
    const int wn   = warp & 1;
    const int qr   = lane >> 2;
    const int qc   = lane & 3;
    const int tile0 = blockIdx.y * 8;           // row-16-tile base
    const int n80   = blockIdx.x * NB8;
    const int K16   = K >> 4;
    const int nkt   = K >> 5;

    float acc[2][NF][4];
    #pragma unroll
    for (int i = 0; i < 2; i++)
        #pragma unroll
        for (int j = 0; j < NF; j++)
            #pragma unroll
            for (int r = 0; r < 4; r++) acc[i][j][r] = 0.f;

    auto stage = [&](int kt) {
        int buf = kt & 1, s0 = kt * 2;
        #pragma unroll
        for (int c = tid; c < A_U4; c += 256) {
            int t = c >> 6, r = c & 63, srel = r >> 5, ln = r & 31;
            size_t go = ((size_t)(tile0 + t) * K16 + s0 + srel) * 32 + ln;
            cp16(&sAh[buf * A_U4 + c], Agh + go);
            cp16(&sAl[buf * A_U4 + c], Agl + go);
        }
        #pragma unroll
        for (int c = tid; c < NB8 * 32; c += 256) {
            int blk = c >> 4, j = c & 15;
            int n8 = n80 + (blk >> 1), srel = blk & 1;
            size_t go = (((size_t)n8 * K16 + s0 + srel) << 4) + j;
            char* dh = (char*)sBh + (size_t)buf * B_U2 * 8 + blk * 256 + j * 16;
            char* dl = (char*)sBl + (size_t)buf * B_U2 * 8 + blk * 256 + j * 16;
            cp16(dh, Bgh + go);
            cp16(dl, Bgl + go);
        }
    };

    stage(0);
    cp_commit();

    for (int kt = 0; kt < nkt; kt++) {
        if (kt + 1 < nkt) { stage(kt + 1); cp_commit(); cp_wait<1>(); }
        else              { cp_wait<0>(); }
        __syncthreads();
        int buf = kt & 1;
        #pragma unroll
        for (int s = 0; s < 2; s++) {
            uint4 fah[2], fal[2];
            uint2 fbh[NF], fbl[NF];
            #pragma unroll
            for (int mi = 0; mi < 2; mi++) {
                int o = buf * A_U4 + ((wm * 2 + mi) * 2 + s) * 32 + lane;
                fah[mi] = sAh[o];
                fal[mi] = sAl[o];
            }
            #pragma unroll
            for (int nj = 0; nj < NF; nj++) {
                int o = buf * B_U2 + ((wn * NF + nj) * 2 + s) * 32 + lane;
                fbh[nj] = sBh[o];
                fbl[nj] = sBl[o];
            }
            #pragma unroll
            for (int mi = 0; mi < 2; mi++)
                #pragma unroll
                for (int nj = 0; nj < NF; nj++) {
                    mma_bf16(acc[mi][nj], fah[mi], fbh[nj]);
                    mma_bf16(acc[mi][nj], fah[mi], fbl[nj]);
                    mma_bf16(acc[mi][nj], fal[mi], fbh[nj]);
                }
        }
        __syncthreads();
    }

    if (FRAG_OUT) {
        // emit next-layer frag-order hi/lo, bias+relu fused
        const int Kout16 = Nfull >> 4;
        #pragma unroll
        for (int mi = 0; mi < 2; mi++) {
            int tile = tile0 + wm * 2 + mi;
            #pragma unroll
            for (int njp = 0; njp < NF / 2; njp++) {
                int nj = njp * 2;
                int colb = blockIdx.x * BN + wn * WTN + nj * 8;
                int col = colb + qc * 2;
                float c0 = acc[mi][nj][0] + bias[col];
                float c1 = acc[mi][nj][1] + bias[col + 1];
                float c2 = acc[mi][nj][2] + bias[col];
                float c3 = acc[mi][nj][3] + bias[col + 1];
                float d0 = acc[mi][nj + 1][0] + bias[col + 8];
                float d1 = acc[mi][nj + 1][1] + bias[col + 9];
                float d2 = acc[mi][nj + 1][2] + bias[col + 8];
                float d3 = acc[mi][nj + 1][3] + bias[col + 9];
                if (relu) {
                    c0 = fmaxf(c0, 0.f); c1 = fmaxf(c1, 0.f);
                    c2 = fmaxf(c2, 0.f); c3 = fmaxf(c3, 0.f);
                    d0 = fmaxf(d0, 0.f); d1 = fmaxf(d1, 0.f);
                    d2 = fmaxf(d2, 0.f); d3 = fmaxf(d3, 0.f);
                }
                uint4 uh, ul;
                split2(c0, c1, uh.x, ul.x);
                split2(c2, c3, uh.y, ul.y);
                split2(d0, d1, uh.z, ul.z);
                split2(d2, d3, uh.w, ul.w);
                size_t o = ((size_t)tile * Kout16 + (colb >> 4)) * 32 + lane;
                Oh[o] = uh;
                Ol[o] = ul;
            }
        }
    } else {
        #pragma unroll
        for (int mi = 0; mi < 2; mi++) {
            int r0 = blockIdx.y * 128 + wm * 32 + mi * 16 + qr;
            #pragma unroll
            for (int nj = 0; nj < NF; nj++) {
                int col = blockIdx.x * BN + wn * WTN + nj * 8 + qc * 2;
                float bx = bias ? bias[col] : 0.f;
                float by = bias ? bias[col + 1] : 0.f;
                *(float2*)&C[(size_t)r0 * Nfull + col] =
                    make_float2(acc[mi][nj][0] + bx, acc[mi][nj][1] + by);
                *(float2*)&C[(size_t)(r0 + 8) * Nfull + col] =
                    make_float2(acc[mi][nj][2] + bx, acc[mi][nj][3] + by);
            }
        }
    }
}

// ---------------------------------------------------------------------------
extern "C" void kernel_launch(void* const* d_in, const int* in_sizes, int n_in,
                              void* d_out, int out_size) {
    const float* x   = (const float*)d_in[0];
    const int*   ei  = (const int*)d_in[1];
    const float* W1l = (const float*)d_in[2];
    const float* W1r = (const float*)d_in[3];
    const float* b1  = (const float*)d_in[4];
    const float* W2l = (const float*)d_in[5];
    const float* W2r = (const float*)d_in[6];
    const float* b2  = (const float*)d_in[7];
    const float* W3l = (const float*)d_in[8];
    const float* W3r = (const float*)d_in[9];
    const float* b3  = (const float*)d_in[10];
    float* out = (float*)d_out;

    const int N = N_NODES;
    const int E = E_EDGES;

    uint4 *a1h, *a1l, *h1h, *h1l, *h2h, *h2l;
    uint4 *w1h, *w1l, *w2lh, *w2ll, *w2rh, *w2rl, *w3lh, *w3ll, *w3rh, *w3rl;
    float *p2l, *p2r, *p3l, *p3r;
    cudaGetSymbolAddress((void**)&a1h, g_a1h);   cudaGetSymbolAddress((void**)&a1l, g_a1l);
    cudaGetSymbolAddress((void**)&h1h, g_h1h);   cudaGetSymbolAddress((void**)&h1l, g_h1l);
    cudaGetSymbolAddress((void**)&h2h, g_h2h);   cudaGetSymbolAddress((void**)&h2l, g_h2l);
    cudaGetSymbolAddress((void**)&w1h, g_w1h);   cudaGetSymbolAddress((void**)&w1l, g_w1l);
    cudaGetSymbolAddress((void**)&w2lh, g_w2lh); cudaGetSymbolAddress((void**)&w2ll, g_w2ll);
    cudaGetSymbolAddress((void**)&w2rh, g_w2rh); cudaGetSymbolAddress((void**)&w2rl, g_w2rl);
    cudaGetSymbolAddress((void**)&w3lh, g_w3lh); cudaGetSymbolAddress((void**)&w3ll, g_w3ll);
    cudaGetSymbolAddress((void**)&w3rh, g_w3rh); cudaGetSymbolAddress((void**)&w3rl, g_w3rl);
    cudaGetSymbolAddress((void**)&p2l, g_p2l);   cudaGetSymbolAddress((void**)&p2r, g_p2r);
    cudaGetSymbolAddress((void**)&p3l, g_p3l);   cudaGetSymbolAddress((void**)&p3r, g_p3r);

    const int TB = 256;
    dim3 gN((N + TB - 1) / TB);
    dim3 gE((E + TB - 1) / TB);
    dim3 gE2((2 * E + TB - 1) / TB);
    dim3 gWarp(((size_t)N * 32 + TB - 1) / TB);

    // ---- CSR ----
    detect_kernel<<<1, 1>>>(ei);
    convert_kernel<<<gE2, TB>>>(ei, 2 * E);
    zero_cnt_kernel<<<gN, TB>>>(N);
    hist_kernel<<<gE, TB>>>(E);
    scan_kernel<<<1, 1024>>>(N);
    cursor_kernel<<<gN, TB>>>(N);
    fill_kernel<<<gE, TB>>>(E);

    // ---- operand prep ----
    xprep_kernel<<<(N * 32 + TB - 1) / TB, TB>>>(x, (unsigned*)a1h, (unsigned*)a1l, N);
    wprep_kernel<<<(64 * 256 + TB - 1) / TB, TB>>>(W1l, 128, 256, 0, 256,
                                                   (unsigned*)w1h, (unsigned*)w1l);
    wprep_kernel<<<(64 * 256 + TB - 1) / TB, TB>>>(W1r, 128, 256, 128, 256,
                                                   (unsigned*)w1h, (unsigned*)w1l);
    wprep_kernel<<<(128 * 128 + TB - 1) / TB, TB>>>(W2l, 256, 128, 0, 256,
                                                    (unsigned*)w2lh, (unsigned*)w2ll);
    wprep_kernel<<<(128 * 128 + TB - 1) / TB, TB>>>(W2r, 256, 128, 0, 256,
                                                    (unsigned*)w2rh, (unsigned*)w2rl);
    wprep_kernel<<<(64 * 64 + TB - 1) / TB, TB>>>(W3l, 128, 64, 0, 128,
                                                  (unsigned*)w3lh, (unsigned*)w3ll);
    wprep_kernel<<<(64 * 64 + TB - 1) / TB, TB>>>(W3r, 128, 64, 0, 128,
                                                  (unsigned*)w3rh, (unsigned*)w3rl);

    const int GY = ROWS_PAD / 128;   // 782
    const size_t SM128 = 65536, SM64 = 49152;
    cudaFuncSetAttribute(gemm_bf16_kernel<128, true>,
                         cudaFuncAttributeMaxDynamicSharedMemorySize, SM128);
    cudaFuncSetAttribute(gemm_bf16_kernel<128, false>,
                         cudaFuncAttributeMaxDynamicSharedMemorySize, SM128);
    cudaFuncSetAttribute(gemm_bf16_kernel<64, false>,
                         cudaFuncAttributeMaxDynamicSharedMemorySize, SM64);

    // ---- Layer 1: agg(x) into a1[k<128]; fused K=256 GEMM -> h1 frag ----
    agg_mean_frag_kernel<<<gWarp, TB>>>(x, (unsigned*)a1h, (unsigned*)a1l, N);
    gemm_bf16_kernel<128, true><<<dim3(2, GY), 256, SM128>>>(
        a1h, a1l, w1h, w1l, 256, 256, b1, (float*)0, h1h, h1l, 1);

    // ---- Layer 2 ----
    gemm_bf16_kernel<128, false><<<dim3(1, GY), 256, SM128>>>(
        h1h, h1l, w2lh, w2ll, 256, 128, (const float*)0, p2l, (uint4*)0, (uint4*)0, 0);
    gemm_bf16_kernel<128, false><<<dim3(1, GY), 256, SM128>>>(
        h1h, h1l, w2rh, w2rl, 256, 128, b2, p2r, (uint4*)0, (uint4*)0, 0);
    agg_add_relu_frag_kernel<<<gWarp, TB>>>(p2l, p2r, (unsigned*)h2h, (unsigned*)h2l, N);

    // ---- Layer 3 ----
    gemm_bf16_kernel<64, false><<<dim3(1, GY), 256, SM64>>>(
        h2h, h2l, w3lh, w3ll, 128, 64, (const float*)0, p3l, (uint4*)0, (uint4*)0, 0);
    gemm_bf16_kernel<64, false><<<dim3(1, GY), 256, SM64>>>(
        h2h, h2l, w3rh, w3rl, 128, 64, b3, p3r, (uint4*)0, (uint4*)0, 0);
    agg_add_lsm64_kernel<<<gWarp, TB>>>(p3l, p3r, out, N);
}

// round 17
// speedup vs baseline: 2.2328x; 1.0264x over previous
#include <cuda_runtime.h>
#include <cuda_bf16.h>
#include <math.h>

// ---------------------------------------------------------------------------
// GraphSAGE (3-layer) on GB300 — split-bf16 tensor-core edition, v2.
// L2/L3 dual GEMMs merged into single launches over concatenated N
// (W2l||W2r -> [256,256], W3l||W3r -> [128,128]); A operands read once.
// ---------------------------------------------------------------------------

#define N_NODES 100000
#define E_EDGES 600000
#define ROWS_PAD 100096   // 782 * 128

// ---- frag-order operand buffers ----
__device__ uint4 g_a1h[(size_t)ROWS_PAD * 32];  // [agg | x] K=256 hi
__device__ uint4 g_a1l[(size_t)ROWS_PAD * 32];
__device__ uint4 g_h1h[(size_t)ROWS_PAD * 32];  // h1 K=256
__device__ uint4 g_h1l[(size_t)ROWS_PAD * 32];
__device__ uint4 g_h2h[(size_t)ROWS_PAD * 16];  // h2 K=128
__device__ uint4 g_h2l[(size_t)ROWS_PAD * 16];
__device__ uint4 g_w1h[8192], g_w1l[8192];      // [W1l;W1r] K=256,N=256
__device__ uint4 g_w2h[8192], g_w2l[8192];      // [W2l|W2r] K=256,N=256
__device__ uint4 g_w3h[2048], g_w3l[2048];      // [W3l|W3r] K=128,N=128

// ---- fp32 scratch (combined outputs) ----
__device__ float g_p2[(size_t)ROWS_PAD * 256];  // [proj_l | proj_r]
__device__ float g_p3[(size_t)ROWS_PAD * 128];
__device__ float g_bias2[256];                  // [0...0 | b2]
__device__ float g_bias3[128];                  // [0...0 | b3]

// ---- CSR ----
__device__ int g_rowptr[N_NODES + 1];
__device__ int g_cnt[N_NODES];
__device__ int g_esrc[E_EDGES];
__device__ int g_edge[2 * E_EDGES];
__device__ int g_is64;

// ---------------------------------------------------------------------------
// helpers
// ---------------------------------------------------------------------------
__device__ __forceinline__ void split2(float a, float b, unsigned& hi, unsigned& lo) {
    __nv_bfloat16 ah = __float2bfloat16(a);
    __nv_bfloat16 bh = __float2bfloat16(b);
    __nv_bfloat16 al = __float2bfloat16(a - __bfloat162float(ah));
    __nv_bfloat16 bl = __float2bfloat16(b - __bfloat162float(bh));
    hi = (unsigned)__bfloat16_as_ushort(ah) | ((unsigned)__bfloat16_as_ushort(bh) << 16);
    lo = (unsigned)__bfloat16_as_ushort(al) | ((unsigned)__bfloat16_as_ushort(bl) << 16);
}

__device__ __forceinline__ size_t fragA_u32(int m, int k, int K) {
    return ((((size_t)(m >> 4)) * (K >> 4) + (k >> 4)) * 32 +
            (((m & 7) << 2) | ((k & 7) >> 1))) * 4 +
           ((m >> 3) & 1) + (((k >> 3) & 1) << 1);
}
__device__ __forceinline__ size_t fragB_u32(int k, int n, int K) {
    return ((((size_t)(n >> 3)) * (K >> 4) + (k >> 4)) * 32 +
            (((n & 7) << 2) | ((k & 7) >> 1))) * 2 +
           ((k >> 3) & 1);
}

__device__ __forceinline__ void cp16(void* dst, const void* src) {
    unsigned d = (unsigned)__cvta_generic_to_shared(dst);
    asm volatile("cp.async.cg.shared.global [%0], [%1], 16;" :: "r"(d), "l"(src));
}
__device__ __forceinline__ void cp_commit() { asm volatile("cp.async.commit_group;"); }
template <int N>
__device__ __forceinline__ void cp_wait() { asm volatile("cp.async.wait_group %0;" :: "n"(N)); }

__device__ __forceinline__ void mma_bf16(float* c, const uint4& a, const uint2& b) {
    asm volatile(
        "mma.sync.aligned.m16n8k16.row.col.f32.bf16.bf16.f32 "
        "{%0,%1,%2,%3},{%4,%5,%6,%7},{%8,%9},{%0,%1,%2,%3};"
        : "+f"(c[0]), "+f"(c[1]), "+f"(c[2]), "+f"(c[3])
        : "r"(a.x), "r"(a.y), "r"(a.z), "r"(a.w), "r"(b.x), "r"(b.y));
}

// ---------------------------------------------------------------------------
// Edge dtype detection + CSR build (validated)
// ---------------------------------------------------------------------------
__global__ void detect_kernel(const int* __restrict__ buf) {
    if (blockIdx.x == 0 && threadIdx.x == 0) {
        int all0 = 1;
        for (int i = 0; i < 128; i++)
            if (buf[2 * i + 1] != 0) { all0 = 0; break; }
        g_is64 = all0;
    }
}
__global__ void convert_kernel(const int* __restrict__ buf, int e2) {
    int i = blockIdx.x * blockDim.x + threadIdx.x;
    if (i < e2) {
        int v = g_is64 ? buf[2 * i] : buf[i];
        g_edge[i] = min(max(v, 0), N_NODES - 1);
    }
}
__global__ void zero_cnt_kernel(int n) {
    int i = blockIdx.x * blockDim.x + threadIdx.x;
    if (i < n) g_cnt[i] = 0;
}
__global__ void hist_kernel(int e) {
    int i = blockIdx.x * blockDim.x + threadIdx.x;
    if (i < e) atomicAdd(&g_cnt[g_edge[E_EDGES + i]], 1);
}
__global__ void scan_kernel(int n) {
    const int T = 1024;
    __shared__ int sums[T];
    int tid = threadIdx.x;
    int chunk = (n + T - 1) / T;
    int beg = min(tid * chunk, n);
    int end = min(beg + chunk, n);
    int s = 0;
    for (int i = beg; i < end; i++) s += g_cnt[i];
    sums[tid] = s;
    __syncthreads();
    for (int off = 1; off < T; off <<= 1) {
        int t = (tid >= off) ? sums[tid - off] : 0;
        __syncthreads();
        sums[tid] += t;
        __syncthreads();
    }
    int run = sums[tid] - s;
    for (int i = beg; i < end; i++) { g_rowptr[i] = run; run += g_cnt[i]; }
    if (tid == T - 1) g_rowptr[n] = sums[T - 1];
}
__global__ void cursor_kernel(int n) {
    int i = blockIdx.x * blockDim.x + threadIdx.x;
    if (i < n) g_cnt[i] = g_rowptr[i];
}
__global__ void fill_kernel(int e) {
    int i = blockIdx.x * blockDim.x + threadIdx.x;
    if (i < e) {
        int d = g_edge[E_EDGES + i];
        int pos = atomicAdd(&g_cnt[d], 1);
        if (pos >= 0 && pos < E_EDGES) g_esrc[pos] = g_edge[i];
    }
}

// ---------------------------------------------------------------------------
// Operand preparation
// ---------------------------------------------------------------------------
__global__ void xprep_kernel(const float* __restrict__ X,
                             unsigned* __restrict__ dh, unsigned* __restrict__ dl, int n) {
    int idx = blockIdx.x * blockDim.x + threadIdx.x;
    if (idx >= n * 32) return;
    int m = idx >> 5, j = idx & 31;
    float4 v = ((const float4*)X)[(size_t)m * 32 + j];
    unsigned h0, l0, h1, l1;
    split2(v.x, v.y, h0, l0);
    split2(v.z, v.w, h1, l1);
    size_t o = fragA_u32(m, 4 * j + 128, 256);
    dh[o] = h0; dl[o] = l0; dh[o + 4] = h1; dl[o + 4] = l1;
}

// weight [K x Nf] fp32 -> frag-order hi/lo at (koff, noff) inside Ktot space
__global__ void wprep_kernel(const float* __restrict__ W, int K, int Nf,
                             int koff, int noff, int Ktot,
                             unsigned* __restrict__ dh, unsigned* __restrict__ dl) {
    int idx = blockIdx.x * blockDim.x + threadIdx.x;
    if (idx >= (K >> 1) * Nf) return;
    int n = idx % Nf, k = (idx / Nf) * 2;
    unsigned h, l;
    split2(W[(size_t)k * Nf + n], W[(size_t)(k + 1) * Nf + n], h, l);
    size_t o = fragB_u32(k + koff, n + noff, Ktot);
    dh[o] = h; dl[o] = l;
}

__global__ void biasprep_kernel(const float* __restrict__ b2,
                                const float* __restrict__ b3) {
    int i = threadIdx.x;                       // 256 threads
    g_bias2[i] = (i < 128) ? 0.f : b2[i - 128];
    if (i < 128) g_bias3[i] = (i < 64) ? 0.f : b3[i - 64];
}

// ---------------------------------------------------------------------------
// Aggregation kernels (one warp per node)
// ---------------------------------------------------------------------------
__global__ void agg_mean_frag_kernel(const float* __restrict__ X,
                                     unsigned* __restrict__ dh,
                                     unsigned* __restrict__ dl, int n) {
    int gid  = blockIdx.x * blockDim.x + threadIdx.x;
    int node = gid >> 5;
    int lane = gid & 31;
    if (node >= n) return;
    int s0 = g_rowptr[node], s1 = g_rowptr[node + 1];
    float4 acc = make_float4(0.f, 0.f, 0.f, 0.f);
    for (int j = s0; j < s1; j++) {
        int s = g_esrc[j];
        float4 v = ((const float4*)(X + (size_t)s * 128))[lane];
        acc.x += v.x; acc.y += v.y; acc.z += v.z; acc.w += v.w;
    }
    float inv = 1.0f / (float)max(s1 - s0, 1);
    acc.x *= inv; acc.y *= inv; acc.z *= inv; acc.w *= inv;
    unsigned h0, l0, h1, l1;
    split2(acc.x, acc.y, h0, l0);
    split2(acc.z, acc.w, h1, l1);
    size_t o = fragA_u32(node, 4 * lane, 256);
    dh[o] = h0; dl[o] = l0; dh[o + 4] = h1; dl[o + 4] = l1;
}

// P[N,256]: cols 0-127 = proj_l (gathered), cols 128-255 = proj_r (self, bias'd)
__global__ void agg_add_relu_frag_kernel(const float* __restrict__ P,
                                         unsigned* __restrict__ dh,
                                         unsigned* __restrict__ dl, int n) {
    int gid  = blockIdx.x * blockDim.x + threadIdx.x;
    int node = gid >> 5;
    int lane = gid & 31;
    if (node >= n) return;
    int s0 = g_rowptr[node], s1 = g_rowptr[node + 1];
    float4 acc = make_float4(0.f, 0.f, 0.f, 0.f);
    for (int j = s0; j < s1; j++) {
        int s = g_esrc[j];
        float4 v = *(const float4*)(P + (size_t)s * 256 + lane * 4);
        acc.x += v.x; acc.y += v.y; acc.z += v.z; acc.w += v.w;
    }
    float inv = 1.0f / (float)max(s1 - s0, 1);
    float4 r = *(const float4*)(P + (size_t)node * 256 + 128 + lane * 4);
    float o0 = fmaxf(acc.x * inv + r.x, 0.f);
    float o1 = fmaxf(acc.y * inv + r.y, 0.f);
    float o2 = fmaxf(acc.z * inv + r.z, 0.f);
    float o3 = fmaxf(acc.w * inv + r.w, 0.f);
    unsigned h0, l0, h1, l1;
    split2(o0, o1, h0, l0);
    split2(o2, o3, h1, l1);
    size_t o = fragA_u32(node, 4 * lane, 128);
    dh[o] = h0; dl[o] = l0; dh[o + 4] = h1; dl[o + 4] = l1;
}

// P[N,128]: cols 0-63 = proj_l (gathered), cols 64-127 = proj_r (self, bias'd)
__global__ void agg_add_lsm64_kernel(const float* __restrict__ P,
                                     float* __restrict__ out, int n) {
    int gid  = blockIdx.x * blockDim.x + threadIdx.x;
    int node = gid >> 5;
    int lane = gid & 31;
    if (node >= n) return;
    int s0 = g_rowptr[node], s1 = g_rowptr[node + 1];
    float2 acc = make_float2(0.f, 0.f);
    for (int j = s0; j < s1; j++) {
        int s = g_esrc[j];
        float2 v = *(const float2*)(P + (size_t)s * 128 + lane * 2);
        acc.x += v.x; acc.y += v.y;
    }
    float inv = 1.0f / (float)max(s1 - s0, 1);
    float2 r = *(const float2*)(P + (size_t)node * 128 + 64 + lane * 2);
    float2 v;
    v.x = acc.x * inv + r.x;
    v.y = acc.y * inv + r.y;
    float m = fmaxf(v.x, v.y);
    #pragma unroll
    for (int off = 16; off >= 1; off >>= 1)
        m = fmaxf(m, __shfl_xor_sync(0xFFFFFFFFu, m, off));
    float se = expf(v.x - m) + expf(v.y - m);
    #pragma unroll
    for (int off = 16; off >= 1; off >>= 1)
        se += __shfl_xor_sync(0xFFFFFFFFu, se, off);
    float lse = m + logf(se);
    ((float2*)(out + (size_t)node * 64))[lane] = make_float2(v.x - lse, v.y - lse);
}

// ---------------------------------------------------------------------------
// Split-bf16 GEMM: C[M,Nfull] = A @ B (+bias)(+relu), 3 mma terms.
// BM=128, BK=32, 256 threads (8 warps, 4x2). FRAG_OUT: emit frag-order hi/lo.
// ---------------------------------------------------------------------------
template <int BN, bool FRAG_OUT>
__global__ __launch_bounds__(256)
void gemm_bf16_kernel(const uint4* __restrict__ Agh, const uint4* __restrict__ Agl,
                      const uint4* __restrict__ Bgh, const uint4* __restrict__ Bgl,
                      int K, int Nfull, const float* __restrict__ bias,
                      float* __restrict__ C,
                      uint4* __restrict__ Oh, uint4* __restrict__ Ol,
                      int relu) {
    constexpr int A_U4 = 512;
    constexpr int NB8  = BN / 8;
    constexpr int B_U2 = NB8 * 64;
    constexpr int WTN  = BN / 2;
    constexpr int NF   = WTN / 8;

    extern __shared__ char sm[];
    uint4* sAh = (uint4*)sm;
    uint4* sAl = sAh + 2 * A_U4;
    uint2* sBh = (uint2*)(sAl + 2 * A_U4);
    uint2* sBl = sBh + 2 * B_U2;

    const int tid  = threadIdx.x;
    const int warp = tid >> 5;
    const int lane = tid & 31;
    const int wm   = warp >> 1;
    const int wn   = warp & 1;
    const int qr   = lane >> 2;
    const int qc   = lane & 3;
    const int tile0 = blockIdx.y * 8;
    const int n80   = blockIdx.x * NB8;
    const int K16   = K >> 4;
    const int nkt   = K >> 5;

    float acc[2][NF][4];
    #pragma unroll
    for (int i = 0; i < 2; i++)
        #pragma unroll
        for (int j = 0; j < NF; j++)
            #pragma unroll
            for (int r = 0; r < 4; r++) acc[i][j][r] = 0.f;

    auto stage = [&](int kt) {
        int buf = kt & 1, s0 = kt * 2;
        #pragma unroll
        for (int c = tid; c < A_U4; c += 256) {
            int t = c >> 6, r = c & 63, srel = r >> 5, ln = r & 31;
            size_t go = ((size_t)(tile0 + t) * K16 + s0 + srel) * 32 + ln;
            cp16(&sAh[buf * A_U4 + c], Agh + go);
            cp16(&sAl[buf * A_U4 + c], Agl + go);
        }
        #pragma unroll
        for (int c = tid; c < NB8 * 32; c += 256) {
            int blk = c >> 4, j = c & 15;
            int n8 = n80 + (blk >> 1), srel = blk & 1;
            size_t go = (((size_t)n8 * K16 + s0 + srel) << 4) + j;
            char* dh = (char*)sBh + (size_t)buf * B_U2 * 8 + blk * 256 + j * 16;
            char* dl = (char*)sBl + (size_t)buf * B_U2 * 8 + blk * 256 + j * 16;
            cp16(dh, Bgh + go);
            cp16(dl, Bgl + go);
        }
    };

    stage(0);
    cp_commit();

    for (int kt = 0; kt < nkt; kt++) {
        if (kt + 1 < nkt) { stage(kt + 1); cp_commit(); cp_wait<1>(); }
        else              { cp_wait<0>(); }
        __syncthreads();
        int buf = kt & 1;
        #pragma unroll
        for (int s = 0; s < 2; s++) {
            uint4 fah[2], fal[2];
            uint2 fbh[NF], fbl[NF];
            #pragma unroll
            for (int mi = 0; mi < 2; mi++) {
                int o = buf * A_U4 + ((wm * 2 + mi) * 2 + s) * 32 + lane;
                fah[mi] = sAh[o];
                fal[mi] = sAl[o];
            }
            #pragma unroll
            for (int nj = 0; nj < NF; nj++) {
                int o = buf * B_U2 + ((wn * NF + nj) * 2 + s) * 32 + lane;
                fbh[nj] = sBh[o];
                fbl[nj] = sBl[o];
            }
            #pragma unroll
            for (int mi = 0; mi < 2; mi++)
                #pragma unroll
                for (int nj = 0; nj < NF; nj++) {
                    mma_bf16(acc[mi][nj], fah[mi], fbh[nj]);
                    mma_bf16(acc[mi][nj], fah[mi], fbl[nj]);
                    mma_bf16(acc[mi][nj], fal[mi], fbh[nj]);
                }
        }
        __syncthreads();
    }

    if (FRAG_OUT) {
        const int Kout16 = Nfull >> 4;
        #pragma unroll
        for (int mi = 0; mi < 2; mi++) {
            int tile = tile0 + wm * 2 + mi;
            #pragma unroll
            for (int njp = 0; njp < NF / 2; njp++) {
                int nj = njp * 2;
                int colb = blockIdx.x * BN + wn * WTN + nj * 8;
                int col = colb + qc * 2;
                float c0 = acc[mi][nj][0] + bias[col];
                float c1 = acc[mi][nj][1] + bias[col + 1];
                float c2 = acc[mi][nj][2] + bias[col];
                float c3 = acc[mi][nj][3] + bias[col + 1];
                float d0 = acc[mi][nj + 1][0] + bias[col + 8];
                float d1 = acc[mi][nj + 1][1] + bias[col + 9];
                float d2 = acc[mi][nj + 1][2] + bias[col + 8];
                float d3 = acc[mi][nj + 1][3] + bias[col + 9];
                if (relu) {
                    c0 = fmaxf(c0, 0.f); c1 = fmaxf(c1, 0.f);
                    c2 = fmaxf(c2, 0.f); c3 = fmaxf(c3, 0.f);
                    d0 = fmaxf(d0, 0.f); d1 = fmaxf(d1, 0.f);
                    d2 = fmaxf(d2, 0.f); d3 = fmaxf(d3, 0.f);
                }
                uint4 uh, ul;
                split2(c0, c1, uh.x, ul.x);
                split2(c2, c3, uh.y, ul.y);
                split2(d0, d1, uh.z, ul.z);
                split2(d2, d3, uh.w, ul.w);
                size_t o = ((size_t)tile * Kout16 + (colb >> 4)) * 32 + lane;
                Oh[o] = uh;
                Ol[o] = ul;
            }
        }
    } else {
        #pragma unroll
        for (int mi = 0; mi < 2; mi++) {
            int r0 = blockIdx.y * 128 + wm * 32 + mi * 16 + qr;
            #pragma unroll
            for (int nj = 0; nj < NF; nj++) {
                int col = blockIdx.x * BN + wn * WTN + nj * 8 + qc * 2;
                float bx = bias ? bias[col] : 0.f;
                float by = bias ? bias[col + 1] : 0.f;
                *(float2*)&C[(size_t)r0 * Nfull + col] =
                    make_float2(acc[mi][nj][0] + bx, acc[mi][nj][1] + by);
                *(float2*)&C[(size_t)(r0 + 8) * Nfull + col] =
                    make_float2(acc[mi][nj][2] + bx, acc[mi][nj][3] + by);
            }
        }
    }
}

// ---------------------------------------------------------------------------
extern "C" void kernel_launch(void* const* d_in, const int* in_sizes, int n_in,
                              void* d_out, int out_size) {
    const float* x   = (const float*)d_in[0];
    const int*   ei  = (const int*)d_in[1];
    const float* W1l = (const float*)d_in[2];
    const float* W1r = (const float*)d_in[3];
    const float* b1  = (const float*)d_in[4];
    const float* W2l = (const float*)d_in[5];
    const float* W2r = (const float*)d_in[6];
    const float* b2  = (const float*)d_in[7];
    const float* W3l = (const float*)d_in[8];
    const float* W3r = (const float*)d_in[9];
    const float* b3  = (const float*)d_in[10];
    float* out = (float*)d_out;

    const int N = N_NODES;
    const int E = E_EDGES;

    uint4 *a1h, *a1l, *h1h, *h1l, *h2h, *h2l;
    uint4 *w1h, *w1l, *w2h, *w2l, *w3h, *w3l;
    float *p2, *p3, *bias2, *bias3;
    cudaGetSymbolAddress((void**)&a1h, g_a1h);  cudaGetSymbolAddress((void**)&a1l, g_a1l);
    cudaGetSymbolAddress((void**)&h1h, g_h1h);  cudaGetSymbolAddress((void**)&h1l, g_h1l);
    cudaGetSymbolAddress((void**)&h2h, g_h2h);  cudaGetSymbolAddress((void**)&h2l, g_h2l);
    cudaGetSymbolAddress((void**)&w1h, g_w1h);  cudaGetSymbolAddress((void**)&w1l, g_w1l);
    cudaGetSymbolAddress((void**)&w2h, g_w2h);  cudaGetSymbolAddress((void**)&w2l, g_w2l);
    cudaGetSymbolAddress((void**)&w3h, g_w3h);  cudaGetSymbolAddress((void**)&w3l, g_w3l);
    cudaGetSymbolAddress((void**)&p2, g_p2);    cudaGetSymbolAddress((void**)&p3, g_p3);
    cudaGetSymbolAddress((void**)&bias2, g_bias2);
    cudaGetSymbolAddress((void**)&bias3, g_bias3);

    const int TB = 256;
    dim3 gN((N + TB - 1) / TB);
    dim3 gE((E + TB - 1) / TB);
    dim3 gE2((2 * E + TB - 1) / TB);
    dim3 gWarp(((size_t)N * 32 + TB - 1) / TB);

    // ---- CSR ----
    detect_kernel<<<1, 1>>>(ei);
    convert_kernel<<<gE2, TB>>>(ei, 2 * E);
    zero_cnt_kernel<<<gN, TB>>>(N);
    hist_kernel<<<gE, TB>>>(E);
    scan_kernel<<<1, 1024>>>(N);
    cursor_kernel<<<gN, TB>>>(N);
    fill_kernel<<<gE, TB>>>(E);

    // ---- operand prep ----
    xprep_kernel<<<(N * 32 + TB - 1) / TB, TB>>>(x, (unsigned*)a1h, (unsigned*)a1l, N);
    wprep_kernel<<<(64 * 256 + TB - 1) / TB, TB>>>(W1l, 128, 256, 0, 0, 256,
                                                   (unsigned*)w1h, (unsigned*)w1l);
    wprep_kernel<<<(64 * 256 + TB - 1) / TB, TB>>>(W1r, 128, 256, 128, 0, 256,
                                                   (unsigned*)w1h, (unsigned*)w1l);
    wprep_kernel<<<(128 * 128 + TB - 1) / TB, TB>>>(W2l, 256, 128, 0, 0, 256,
                                                    (unsigned*)w2h, (unsigned*)w2l);
    wprep_kernel<<<(128 * 128 + TB - 1) / TB, TB>>>(W2r, 256, 128, 0, 128, 256,
                                                    (unsigned*)w2h, (unsigned*)w2l);
    wprep_kernel<<<(64 * 64 + TB - 1) / TB, TB>>>(W3l, 128, 64, 0, 0, 128,
                                                  (unsigned*)w3h, (unsigned*)w3l);
    wprep_kernel<<<(64 * 64 + TB - 1) / TB, TB>>>(W3r, 128, 64, 0, 64, 128,
                                                  (unsigned*)w3h, (unsigned*)w3l);
    biasprep_kernel<<<1, 256>>>(b2, b3);

    const int GY = ROWS_PAD / 128;   // 782
    const size_t SM128 = 65536, SM64 = 49152;
    cudaFuncSetAttribute(gemm_bf16_kernel<128, true>,
                         cudaFuncAttributeMaxDynamicSharedMemorySize, SM128);
    cudaFuncSetAttribute(gemm_bf16_kernel<128, false>,
                         cudaFuncAttributeMaxDynamicSharedMemorySize, SM128);
    cudaFuncSetAttribute(gemm_bf16_kernel<64, false>,
                         cudaFuncAttributeMaxDynamicSharedMemorySize, SM64);

    // ---- Layer 1: agg(x) into a1[k<128]; fused K=256 GEMM -> h1 frag ----
    agg_mean_frag_kernel<<<gWarp, TB>>>(x, (unsigned*)a1h, (unsigned*)a1l, N);
    gemm_bf16_kernel<128, true><<<dim3(2, GY), 256, SM128>>>(
        a1h, a1l, w1h, w1l, 256, 256, b1, (float*)0, h1h, h1l, 1);

    // ---- Layer 2: single merged GEMM over N=256 ([W2l|W2r]) ----
    gemm_bf16_kernel<128, false><<<dim3(2, GY), 256, SM128>>>(
        h1h, h1l, w2h, w2l, 256, 256, bias2, p2, (uint4*)0, (uint4*)0, 0);
    agg_add_relu_frag_kernel<<<gWarp, TB>>>(p2, (unsigned*)h2h, (unsigned*)h2l, N);

    // ---- Layer 3: single merged GEMM over N=128 ([W3l|W3r]) ----
    gemm_bf16_kernel<64, false><<<dim3(2, GY), 256, SM64>>>(
        h2h, h2l, w3h, w3l, 128, 128, bias3, p3, (uint4*)0, (uint4*)0, 0);
    agg_add_lsm64_kernel<<<gWarp, TB>>>(p3, out, N);
}